// round 6
// baseline (speedup 1.0000x reference)
#include <cuda_runtime.h>
#include <cuda_bf16.h>
#include <math.h>
#include <stdint.h>

#define DM 1024
#define NH 16
#define HD 64
#define MSL 5000
#define BB 2
#define SS 2048
#define MT (BB*SS)   // 4096 rows total

// Scratch (allocation-free rule: device globals)
__device__ __nv_bfloat16 g_ah[MT*DM];     // GEMM A hi (xpe-split, later o-split)
__device__ __nv_bfloat16 g_al[MT*DM];     // GEMM A lo
__device__ __nv_bfloat16 g_wh[3*DM*DM];   // stacked Wq|Wk|Wv hi (reused for Wo)
__device__ __nv_bfloat16 g_wl[3*DM*DM];
// split-bf16 Q/K/V in [B,H,S,hd] (Q pre-scaled by 1/32)
__device__ __nv_bfloat16 g_qh[MT*DM];
__device__ __nv_bfloat16 g_ql[MT*DM];
__device__ __nv_bfloat16 g_kh[MT*DM];
__device__ __nv_bfloat16 g_kl[MT*DM];
__device__ __nv_bfloat16 g_vh[MT*DM];
__device__ __nv_bfloat16 g_vl[MT*DM];

// ---------------------------------------------------------------------------
// helpers
// ---------------------------------------------------------------------------
__device__ __forceinline__ uint32_t smem_u32(const void* p) {
    uint32_t a;
    asm("{ .reg .u64 t; cvta.to.shared.u64 t, %1; cvt.u32.u64 %0, t; }" : "=r"(a) : "l"(p));
    return a;
}

#define CP16(dst, src) \
    asm volatile("cp.async.cg.shared.global [%0], [%1], 16;" :: "r"(dst), "l"(src))
#define CP_COMMIT()  asm volatile("cp.async.commit_group;" ::: "memory")
#define CP_WAIT(n)   asm volatile("cp.async.wait_group %0;" :: "n"(n) : "memory")

#define LDSM4(r, addr) \
    asm volatile("ldmatrix.sync.aligned.m8n8.x4.shared.b16 {%0,%1,%2,%3}, [%4];" \
        : "=r"((r)[0]), "=r"((r)[1]), "=r"((r)[2]), "=r"((r)[3]) : "r"(addr))

#define LDSM4T(r, addr) \
    asm volatile("ldmatrix.sync.aligned.m8n8.x4.trans.shared.b16 {%0,%1,%2,%3}, [%4];" \
        : "=r"((r)[0]), "=r"((r)[1]), "=r"((r)[2]), "=r"((r)[3]) : "r"(addr))

#define MMA16816(d, a, b0v, b1v) \
    asm volatile("mma.sync.aligned.m16n8k16.row.col.f32.bf16.bf16.f32 " \
        "{%0,%1,%2,%3}, {%4,%5,%6,%7}, {%8,%9}, {%0,%1,%2,%3};" \
        : "+f"((d)[0]), "+f"((d)[1]), "+f"((d)[2]), "+f"((d)[3]) \
        : "r"((a)[0]), "r"((a)[1]), "r"((a)[2]), "r"((a)[3]), "r"(b0v), "r"(b1v))

__device__ __forceinline__ uint32_t pack_bf(float hi, float lo) {
    uint32_t d;
    asm("cvt.rn.bf16x2.f32 %0, %1, %2;" : "=r"(d) : "f"(hi), "f"(lo));
    return d;
}
__device__ __forceinline__ float bf_round(float v) {
    return __bfloat162float(__float2bfloat16(v));
}

// ---------------------------------------------------------------------------
// Kernel 1: fused PE + split:  (x + a*sin_pe + (1-a)*rel) -> (g_ah, g_al)
// ---------------------------------------------------------------------------
__global__ void pe_split_kernel(const float* __restrict__ x,
                                const float* __restrict__ rel,
                                const float* __restrict__ alphap) {
    int idx = blockIdx.x*blockDim.x + threadIdx.x;
    if (idx >= MT*(DM/2)) return;
    int m  = idx >> 9;
    int pp = idx & 511;
    int s  = m & (SS-1);
    float a = alphap[0];
    float freq = __expf(-(float)(2*pp) * (9.210340371976184f/(float)DM));
    float ang = (float)s * freq;
    float sn, cs;
    sincosf(ang, &sn, &cs);
    const float* rr = rel + (size_t)(MSL - SS + s)*DM + 2*pp;
    float2 xv = *(const float2*)(x + (size_t)idx*2);
    float om = 1.0f - a;
    float ox = xv.x + a*sn + om*rr[0];
    float oy = xv.y + a*cs + om*rr[1];
    __nv_bfloat16 hx = __float2bfloat16(ox);
    __nv_bfloat16 hy = __float2bfloat16(oy);
    __nv_bfloat16 lx = __float2bfloat16(ox - __bfloat162float(hx));
    __nv_bfloat16 ly = __float2bfloat16(oy - __bfloat162float(hy));
    *(__nv_bfloat162*)(g_ah + (size_t)idx*2) = __nv_bfloat162(hx, hy);
    *(__nv_bfloat162*)(g_al + (size_t)idx*2) = __nv_bfloat162(lx, ly);
}

// ---------------------------------------------------------------------------
// Kernel 2: fp32 -> (hi, lo) bf16 split (for weights).
// ---------------------------------------------------------------------------
__global__ void split_kernel(const float* __restrict__ src,
                             __nv_bfloat16* __restrict__ hi,
                             __nv_bfloat16* __restrict__ lo, int n4) {
    int i = blockIdx.x*blockDim.x + threadIdx.x;
    if (i >= n4) return;
    float4 v = ((const float4*)src)[i];
    __nv_bfloat16 h0 = __float2bfloat16(v.x);
    __nv_bfloat16 h1 = __float2bfloat16(v.y);
    __nv_bfloat16 h2 = __float2bfloat16(v.z);
    __nv_bfloat16 h3 = __float2bfloat16(v.w);
    __nv_bfloat16 l0 = __float2bfloat16(v.x - __bfloat162float(h0));
    __nv_bfloat16 l1 = __float2bfloat16(v.y - __bfloat162float(h1));
    __nv_bfloat16 l2 = __float2bfloat16(v.z - __bfloat162float(h2));
    __nv_bfloat16 l3 = __float2bfloat16(v.w - __bfloat162float(h3));
    __nv_bfloat162* hp = (__nv_bfloat162*)(hi + (size_t)i*4);
    __nv_bfloat162* lp = (__nv_bfloat162*)(lo + (size_t)i*4);
    hp[0] = __nv_bfloat162(h0, h1); hp[1] = __nv_bfloat162(h2, h3);
    lp[0] = __nv_bfloat162(l0, l1); lp[1] = __nv_bfloat162(l2, l3);
}

// ---------------------------------------------------------------------------
// mma.sync split-bf16 GEMM, 3-stage cp.async pipeline.
// Block 128x128, 256 threads, warp tile 64x32, K-chunk 32.
// mode 0: merged QKV (gridDim.x = 24); n0>>10 selects Q/K/V target + scale.
// mode 3: output projection (gridDim.x = 8), fp32 row-major to outp.
// ---------------------------------------------------------------------------
#define RS    80                     // smem row stride bytes
#define ASZ   (128*RS)               // 10240 per array
#define BUF3  (4*ASZ)                // AH AL BH BL = 40960
#define GEMM_SMEM (3*BUF3)           // 122880
#define CHN   (DM/32)                // 32

__global__ void __launch_bounds__(256, 1) gemm_mma(const __nv_bfloat16* __restrict__ Ah,
                                                   const __nv_bfloat16* __restrict__ Al,
                                                   const float* __restrict__ b0,
                                                   const float* __restrict__ b1,
                                                   const float* __restrict__ b2,
                                                   float* __restrict__ outp,
                                                   int mode) {
    extern __shared__ char smem[];
    const uint32_t sb = smem_u32(smem);
    const int t  = threadIdx.x;
    const int m0 = blockIdx.y * 128;
    const int n0 = blockIdx.x * 128;

    const int wid = t >> 5, l = t & 31;
    const int warpM = wid & 1;
    const int warpN = wid >> 1;
    const int q  = l >> 3, lr = l & 7;

    const __nv_bfloat16* __restrict__ Bh = g_wh;
    const __nv_bfloat16* __restrict__ Bl = g_wl;

    const int ldrow = t >> 1;
    const int ldc   = (t & 1) * 2;
    const size_t a_row_off = (size_t)(m0 + ldrow) * DM;
    const size_t b_row_off = (size_t)(n0 + ldrow) * DM;
    const uint32_t st_off  = (uint32_t)ldrow * RS + (uint32_t)ldc * 16;

    auto stage = [&](int ck) {
        const uint32_t d = sb + (uint32_t)(ck % 3) * BUF3 + st_off;
        const int k0 = ck * 32;
        CP16(d + 0*ASZ +  0, Ah + a_row_off + k0 + ldc*8);
        CP16(d + 0*ASZ + 16, Ah + a_row_off + k0 + ldc*8 + 8);
        CP16(d + 1*ASZ +  0, Al + a_row_off + k0 + ldc*8);
        CP16(d + 1*ASZ + 16, Al + a_row_off + k0 + ldc*8 + 8);
        CP16(d + 2*ASZ +  0, Bh + b_row_off + k0 + ldc*8);
        CP16(d + 2*ASZ + 16, Bh + b_row_off + k0 + ldc*8 + 8);
        CP16(d + 3*ASZ +  0, Bl + b_row_off + k0 + ldc*8);
        CP16(d + 3*ASZ + 16, Bl + b_row_off + k0 + ldc*8 + 8);
        CP_COMMIT();
    };

    float acc[16][4];
    #pragma unroll
    for (int i = 0; i < 16; i++)
        #pragma unroll
        for (int j = 0; j < 4; j++) acc[i][j] = 0.f;

    const uint32_t a_lane = (uint32_t)(warpM*64 + (q & 1)*8 + lr) * RS + (uint32_t)(q >> 1) * 16;
    const uint32_t b_lane = (uint32_t)(warpN*32 + (q >> 1)*8 + lr) * RS + (uint32_t)(q & 1) * 16;

    // prologue: chunks 0 and 1 in flight
    stage(0);
    stage(1);
    CP_WAIT(1);
    __syncthreads();

    for (int ch = 0; ch < CHN; ch++) {
        if (ch + 2 < CHN) stage(ch + 2);

        const uint32_t buf = sb + (uint32_t)(ch % 3) * BUF3;
        #pragma unroll
        for (int ks = 0; ks < 32; ks += 16) {
            const uint32_t kadd = (uint32_t)ks * 2;
            uint32_t ah[4][4], alr[4][4];
            #pragma unroll
            for (int mt = 0; mt < 4; mt++) {
                uint32_t ao = a_lane + (uint32_t)mt * 16 * RS + kadd;
                LDSM4(ah[mt],  buf + 0*ASZ + ao);
                LDSM4(alr[mt], buf + 1*ASZ + ao);
            }
            uint32_t bh[2][4], bl[2][4];
            #pragma unroll
            for (int np = 0; np < 2; np++) {
                uint32_t bo = b_lane + (uint32_t)np * 16 * RS + kadd;
                LDSM4(bh[np], buf + 2*ASZ + bo);
                LDSM4(bl[np], buf + 3*ASZ + bo);
            }
            // three product passes; same-acc MMAs spaced 16 apart
            #pragma unroll
            for (int mt = 0; mt < 4; mt++)
                #pragma unroll
                for (int nt = 0; nt < 4; nt++) {
                    const int np = nt >> 1, h = (nt & 1) * 2;
                    MMA16816(acc[mt*4+nt], ah[mt], bh[np][h], bh[np][h+1]);
                }
            #pragma unroll
            for (int mt = 0; mt < 4; mt++)
                #pragma unroll
                for (int nt = 0; nt < 4; nt++) {
                    const int np = nt >> 1, h = (nt & 1) * 2;
                    MMA16816(acc[mt*4+nt], ah[mt], bl[np][h], bl[np][h+1]);
                }
            #pragma unroll
            for (int mt = 0; mt < 4; mt++)
                #pragma unroll
                for (int nt = 0; nt < 4; nt++) {
                    const int np = nt >> 1, h = (nt & 1) * 2;
                    MMA16816(acc[mt*4+nt], alr[mt], bh[np][h], bh[np][h+1]);
                }
        }

        if (ch + 2 < CHN) { CP_WAIT(1); } else { CP_WAIT(0); }
        if (ch < CHN - 1) __syncthreads();
    }

    // epilogue
    if (mode == 0) {
        const int which = n0 >> 10;                    // 0=Q 1=K 2=V (uniform per CTA)
        const float ascale = (which == 0) ? 0.03125f : 1.0f;
        __nv_bfloat16* oh = (which == 0) ? g_qh : (which == 1) ? g_kh : g_vh;
        __nv_bfloat16* ol = (which == 0) ? g_ql : (which == 1) ? g_kl : g_vl;
        const float* bias = (which == 0) ? b0 : (which == 1) ? b1 : b2;
        const int nloc0 = n0 & 1023;
        #pragma unroll
        for (int nt = 0; nt < 4; nt++) {
            const int n = nloc0 + warpN*32 + nt*8 + (l & 3)*2;
            const float bx = bias[n], by = bias[n+1];
            #pragma unroll
            for (int mt = 0; mt < 4; mt++) {
                const float* d = acc[mt*4 + nt];
                #pragma unroll
                for (int half = 0; half < 2; half++) {
                    const int m = m0 + warpM*64 + mt*16 + (l >> 2) + half*8;
                    float vx = (d[half*2 + 0] + bx) * ascale;
                    float vy = (d[half*2 + 1] + by) * ascale;
                    const int bb = m >> 11, s = m & (SS-1);
                    const int hh = n >> 6, dd = n & 63;
                    size_t o = (size_t)((bb*NH + hh)*SS + s)*HD + dd;
                    __nv_bfloat16 hx = __float2bfloat16(vx);
                    __nv_bfloat16 hy = __float2bfloat16(vy);
                    __nv_bfloat16 lx = __float2bfloat16(vx - __bfloat162float(hx));
                    __nv_bfloat16 ly = __float2bfloat16(vy - __bfloat162float(hy));
                    *(__nv_bfloat162*)(oh + o) = __nv_bfloat162(hx, hy);
                    *(__nv_bfloat162*)(ol + o) = __nv_bfloat162(lx, ly);
                }
            }
        }
    } else {
        #pragma unroll
        for (int nt = 0; nt < 4; nt++) {
            const int n = n0 + warpN*32 + nt*8 + (l & 3)*2;
            const float bx = b0[n], by = b0[n+1];
            #pragma unroll
            for (int mt = 0; mt < 4; mt++) {
                const float* d = acc[mt*4 + nt];
                #pragma unroll
                for (int half = 0; half < 2; half++) {
                    const int m = m0 + warpM*64 + mt*16 + (l >> 2) + half*8;
                    float2 v;
                    v.x = d[half*2 + 0] + bx;
                    v.y = d[half*2 + 1] + by;
                    *(float2*)&outp[(size_t)m*DM + n] = v;
                }
            }
        }
    }
}

// ---------------------------------------------------------------------------
// Flash attention on tensor cores (split-bf16, online softmax) — as round 5.
// ---------------------------------------------------------------------------
#define FRS 144
#define QTILE (128*FRS)
#define KVTILE (64*FRS)
#define KVSTAGE (4*KVTILE)
#define FL_SMEM (2*QTILE + 2*KVSTAGE)

__device__ __forceinline__ void kv_stage(uint32_t dstbase, size_t bhoff, int kv0, int t) {
    const int row = t >> 3;
    const int ch  = t & 7;
    #pragma unroll
    for (int half = 0; half < 2; half++) {
        const int r = row + half*32;
        const uint32_t dro = (uint32_t)r*FRS + (uint32_t)ch*16;
        const size_t sro = bhoff + (size_t)(kv0 + r)*HD + ch*8;
        CP16(dstbase + 0*KVTILE + dro, g_kh + sro);
        CP16(dstbase + 1*KVTILE + dro, g_kl + sro);
        CP16(dstbase + 2*KVTILE + dro, g_vh + sro);
        CP16(dstbase + 3*KVTILE + dro, g_vl + sro);
    }
}

__global__ void __launch_bounds__(256, 1) flash_mma() {
    extern __shared__ char fsm[];
    const uint32_t sb = smem_u32(fsm);
    const int bh = blockIdx.y;
    const int q0 = blockIdx.x * 128;
    const size_t bhoff = (size_t)bh * SS * HD;
    const int t = threadIdx.x, wid = t >> 5, l = t & 31;
    const int q = l >> 3, lr = l & 7;
    const int wq0 = wid * 16;

    {
        const int ch = t & 7;
        #pragma unroll
        for (int p = 0; p < 4; p++) {
            const int row = (t >> 3) + p*32;
            const uint32_t dro = (uint32_t)row*FRS + (uint32_t)ch*16;
            const size_t sro = bhoff + (size_t)(q0 + row)*HD + ch*8;
            CP16(sb + dro, g_qh + sro);
            CP16(sb + QTILE + dro, g_ql + sro);
        }
    }
    kv_stage(sb + 2*QTILE, bhoff, 0, t);
    CP_COMMIT();
    CP_WAIT(0);
    __syncthreads();

    uint32_t qhf[4][4], qlf[4][4];
    #pragma unroll
    for (int kt = 0; kt < 4; kt++) {
        uint32_t ad = sb + (uint32_t)(wq0 + (q & 1)*8 + lr)*FRS + (uint32_t)(q >> 1)*16 + kt*32;
        LDSM4(qhf[kt], ad);
        LDSM4(qlf[kt], ad + QTILE);
    }

    float oacc[8][4];
    #pragma unroll
    for (int i = 0; i < 8; i++)
        #pragma unroll
        for (int j = 0; j < 4; j++) oacc[i][j] = 0.f;
    float mprev0 = -1e30f, mprev1 = -1e30f, lsum0 = 0.f, lsum1 = 0.f;

    for (int ti = 0; ti < SS/64; ti++) {
        if (ti < SS/64 - 1) {
            kv_stage(sb + 2*QTILE + ((ti+1) & 1)*KVSTAGE, bhoff, (ti+1)*64, t);
            CP_COMMIT();
        }
        const uint32_t kb = sb + 2*QTILE + (ti & 1)*KVSTAGE;

        float sacc[8][4];
        #pragma unroll
        for (int i = 0; i < 8; i++)
            #pragma unroll
            for (int j = 0; j < 4; j++) sacc[i][j] = 0.f;

        #pragma unroll
        for (int kt = 0; kt < 4; kt++) {
            uint32_t khf[4][4], klf[4][4];
            #pragma unroll
            for (int np = 0; np < 4; np++) {
                uint32_t ba = kb + (uint32_t)(np*16 + (q >> 1)*8 + lr)*FRS + kt*32 + (q & 1)*16;
                LDSM4(khf[np], ba);
                LDSM4(klf[np], ba + KVTILE);
            }
            #pragma unroll
            for (int nt = 0; nt < 8; nt++) {
                const int np = nt >> 1, h = (nt & 1)*2;
                MMA16816(sacc[nt], qhf[kt], khf[np][h], khf[np][h+1]);
            }
            #pragma unroll
            for (int nt = 0; nt < 8; nt++) {
                const int np = nt >> 1, h = (nt & 1)*2;
                MMA16816(sacc[nt], qhf[kt], klf[np][h], klf[np][h+1]);
            }
            #pragma unroll
            for (int nt = 0; nt < 8; nt++) {
                const int np = nt >> 1, h = (nt & 1)*2;
                MMA16816(sacc[nt], qlf[kt], khf[np][h], khf[np][h+1]);
            }
        }

        float m0 = sacc[0][0], m1 = sacc[0][2];
        #pragma unroll
        for (int nt = 0; nt < 8; nt++) {
            m0 = fmaxf(m0, fmaxf(sacc[nt][0], sacc[nt][1]));
            m1 = fmaxf(m1, fmaxf(sacc[nt][2], sacc[nt][3]));
        }
        m0 = fmaxf(m0, __shfl_xor_sync(0xffffffffu, m0, 1));
        m0 = fmaxf(m0, __shfl_xor_sync(0xffffffffu, m0, 2));
        m1 = fmaxf(m1, __shfl_xor_sync(0xffffffffu, m1, 1));
        m1 = fmaxf(m1, __shfl_xor_sync(0xffffffffu, m1, 2));

        const float mn0 = fmaxf(mprev0, m0);
        const float mn1 = fmaxf(mprev1, m1);
        const float a0 = __expf(mprev0 - mn0);
        const float a1 = __expf(mprev1 - mn1);
        mprev0 = mn0; mprev1 = mn1;

        float rs0 = 0.f, rs1 = 0.f;
        #pragma unroll
        for (int nt = 0; nt < 8; nt++) {
            sacc[nt][0] = __expf(sacc[nt][0] - mn0);
            sacc[nt][1] = __expf(sacc[nt][1] - mn0);
            sacc[nt][2] = __expf(sacc[nt][2] - mn1);
            sacc[nt][3] = __expf(sacc[nt][3] - mn1);
            rs0 += sacc[nt][0] + sacc[nt][1];
            rs1 += sacc[nt][2] + sacc[nt][3];
        }
        rs0 += __shfl_xor_sync(0xffffffffu, rs0, 1);
        rs0 += __shfl_xor_sync(0xffffffffu, rs0, 2);
        rs1 += __shfl_xor_sync(0xffffffffu, rs1, 1);
        rs1 += __shfl_xor_sync(0xffffffffu, rs1, 2);
        lsum0 = lsum0*a0 + rs0;
        lsum1 = lsum1*a1 + rs1;
        #pragma unroll
        for (int nj = 0; nj < 8; nj++) {
            oacc[nj][0] *= a0; oacc[nj][1] *= a0;
            oacc[nj][2] *= a1; oacc[nj][3] *= a1;
        }

        #pragma unroll
        for (int kt = 0; kt < 4; kt++) {
            uint32_t ph[4], pl[4];
            #pragma unroll
            for (int e = 0; e < 4; e++) {
                const float* s0 = sacc[2*kt + (e >> 1)];
                const float x0 = s0[(e & 1)*2], x1 = s0[(e & 1)*2 + 1];
                ph[e] = pack_bf(x1, x0);
                pl[e] = pack_bf(x1 - bf_round(x1), x0 - bf_round(x0));
            }
            uint32_t vhf[4][4], vlf[4][4];
            #pragma unroll
            for (int g = 0; g < 4; g++) {
                uint32_t va = kb + 2*KVTILE + (uint32_t)(kt*16 + (q & 1)*8 + lr)*FRS
                              + (uint32_t)(2*g + (q >> 1))*16;
                LDSM4T(vhf[g], va);
                LDSM4T(vlf[g], va + KVTILE);
            }
            #pragma unroll
            for (int nj = 0; nj < 8; nj++) {
                const int g = nj >> 1, o = (nj & 1)*2;
                MMA16816(oacc[nj], ph, vhf[g][o], vhf[g][o+1]);
            }
            #pragma unroll
            for (int nj = 0; nj < 8; nj++) {
                const int g = nj >> 1, o = (nj & 1)*2;
                MMA16816(oacc[nj], ph, vlf[g][o], vlf[g][o+1]);
            }
            #pragma unroll
            for (int nj = 0; nj < 8; nj++) {
                const int g = nj >> 1, o = (nj & 1)*2;
                MMA16816(oacc[nj], pl, vhf[g][o], vhf[g][o+1]);
            }
        }

        if (ti < SS/64 - 1) {
            CP_WAIT(0);
            __syncthreads();
        }
    }

    const float inv0 = 1.0f / lsum0;
    const float inv1 = 1.0f / lsum1;
    const int r0 = q0 + wq0 + (l >> 2);
    const int bb = bh >> 4, hh = bh & 15;
    #pragma unroll
    for (int nj = 0; nj < 8; nj++) {
        const int col = hh*HD + nj*8 + (l & 3)*2;
        {
            const float e0 = oacc[nj][0]*inv0, e1 = oacc[nj][1]*inv0;
            __nv_bfloat16 h0 = __float2bfloat16(e0), h1 = __float2bfloat16(e1);
            __nv_bfloat16 l0 = __float2bfloat16(e0 - __bfloat162float(h0));
            __nv_bfloat16 l1 = __float2bfloat16(e1 - __bfloat162float(h1));
            size_t o = (size_t)(bb*SS + r0)*DM + col;
            *(__nv_bfloat162*)(g_ah + o) = __nv_bfloat162(h0, h1);
            *(__nv_bfloat162*)(g_al + o) = __nv_bfloat162(l0, l1);
        }
        {
            const float e0 = oacc[nj][2]*inv1, e1 = oacc[nj][3]*inv1;
            __nv_bfloat16 h0 = __float2bfloat16(e0), h1 = __float2bfloat16(e1);
            __nv_bfloat16 l0 = __float2bfloat16(e0 - __bfloat162float(h0));
            __nv_bfloat16 l1 = __float2bfloat16(e1 - __bfloat162float(h1));
            size_t o = (size_t)(bb*SS + r0 + 8)*DM + col;
            *(__nv_bfloat162*)(g_ah + o) = __nv_bfloat162(h0, h1);
            *(__nv_bfloat162*)(g_al + o) = __nv_bfloat162(l0, l1);
        }
    }
}

// ---------------------------------------------------------------------------
extern "C" void kernel_launch(void* const* d_in, const int* in_sizes, int n_in,
                              void* d_out, int out_size) {
    const float* x     = (const float*)d_in[0];
    const float* rel   = (const float*)d_in[1];
    const float* alpha = (const float*)d_in[2];
    const float* Wq    = (const float*)d_in[3];
    const float* bq    = (const float*)d_in[4];
    const float* Wk    = (const float*)d_in[5];
    const float* bk    = (const float*)d_in[6];
    const float* Wv    = (const float*)d_in[7];
    const float* bv    = (const float*)d_in[8];
    const float* Wo    = (const float*)d_in[9];
    const float* bo    = (const float*)d_in[10];
    float* out = (float*)d_out;

    cudaFuncSetAttribute(gemm_mma, cudaFuncAttributeMaxDynamicSharedMemorySize, GEMM_SMEM);
    cudaFuncSetAttribute(flash_mma, cudaFuncAttributeMaxDynamicSharedMemorySize, FL_SMEM);

    __nv_bfloat16 *ah, *al, *wh, *wl;
    cudaGetSymbolAddress((void**)&ah, g_ah);
    cudaGetSymbolAddress((void**)&al, g_al);
    cudaGetSymbolAddress((void**)&wh, g_wh);
    cudaGetSymbolAddress((void**)&wl, g_wl);

    pe_split_kernel<<<(MT*(DM/2) + 255)/256, 256>>>(x, rel, alpha);

    const int nW4 = DM*DM/4;
    split_kernel<<<(nW4 + 255)/256, 256>>>(Wq, wh,            wl,            nW4);
    split_kernel<<<(nW4 + 255)/256, 256>>>(Wk, wh + DM*DM,    wl + DM*DM,    nW4);
    split_kernel<<<(nW4 + 255)/256, 256>>>(Wv, wh + 2*DM*DM,  wl + 2*DM*DM,  nW4);

    gemm_mma<<<dim3(3*DM/128, MT/128), 256, GEMM_SMEM>>>(ah, al, bq, bk, bv, nullptr, 0);

    flash_mma<<<dim3(SS/128, BB*NH), 256, FL_SMEM>>>();

    split_kernel<<<(nW4 + 255)/256, 256>>>(Wo, wh, wl, nW4);
    gemm_mma<<<dim3(DM/128, MT/128), 256, GEMM_SMEM>>>(ah, al, bo, bo, bo, out, 3);
}

// round 7
// speedup vs baseline: 1.3439x; 1.3439x over previous
#include <cuda_runtime.h>
#include <cuda.h>
#include <cuda_bf16.h>
#include <math.h>
#include <stdint.h>

#define DM 1024
#define NH 16
#define HD 64
#define MSL 5000
#define BB 2
#define SS 2048
#define MT (BB*SS)   // 4096 rows total

// Scratch (allocation-free rule: device globals)
__device__ __nv_bfloat16 g_ah[MT*DM];     // GEMM A hi (xpe-split, later o-split)
__device__ __nv_bfloat16 g_al[MT*DM];     // GEMM A lo
__device__ __nv_bfloat16 g_wh[3*DM*DM];   // stacked Wq|Wk|Wv hi (reused for Wo)
__device__ __nv_bfloat16 g_wl[3*DM*DM];
// split-bf16 Q/K/V in [B,H,S,hd] (Q pre-scaled by 1/32)
__device__ __nv_bfloat16 g_qh[MT*DM];
__device__ __nv_bfloat16 g_ql[MT*DM];
__device__ __nv_bfloat16 g_kh[MT*DM];
__device__ __nv_bfloat16 g_kl[MT*DM];
__device__ __nv_bfloat16 g_vh[MT*DM];
__device__ __nv_bfloat16 g_vl[MT*DM];

// ---------------------------------------------------------------------------
// helpers
// ---------------------------------------------------------------------------
__device__ __forceinline__ uint32_t smem_u32(const void* p) {
    uint32_t a;
    asm("{ .reg .u64 t; cvta.to.shared.u64 t, %1; cvt.u32.u64 %0, t; }" : "=r"(a) : "l"(p));
    return a;
}

#define MBAR_INIT(addr, cnt) \
    asm volatile("mbarrier.init.shared.b64 [%0], %1;" :: "r"(addr), "r"(cnt) : "memory")

#define EXPECT_TX(addr, bytes) \
    asm volatile("mbarrier.arrive.expect_tx.shared.b64 _, [%0], %1;" :: "r"(addr), "r"(bytes) : "memory")

#define TMA2D(smem, mapp, x, y, mbar) \
    asm volatile("cp.async.bulk.tensor.2d.shared::cluster.global.tile.mbarrier::complete_tx::bytes " \
        "[%0], [%1, {%2, %3}], [%4];" \
        :: "r"(smem), "l"(mapp), "r"(x), "r"(y), "r"(mbar) : "memory")

__device__ __forceinline__ void mbar_wait(uint32_t addr, uint32_t parity) {
    uint32_t done;
    asm volatile(
        "{\n\t.reg .pred p;\n\t"
        "mbarrier.try_wait.parity.shared.b64 p, [%1], %2;\n\t"
        "selp.b32 %0,1,0,p;\n\t}"
        : "=r"(done) : "r"(addr), "r"(parity) : "memory");
    while (!done) {
        asm volatile(
            "{\n\t.reg .pred p;\n\t"
            "mbarrier.try_wait.parity.shared.b64 p, [%1], %2, 0x989680;\n\t"
            "selp.b32 %0,1,0,p;\n\t}"
            : "=r"(done) : "r"(addr), "r"(parity) : "memory");
    }
}

#define LDSM4(r, addr) \
    asm volatile("ldmatrix.sync.aligned.m8n8.x4.shared.b16 {%0,%1,%2,%3}, [%4];" \
        : "=r"((r)[0]), "=r"((r)[1]), "=r"((r)[2]), "=r"((r)[3]) : "r"(addr))

#define LDSM4T(r, addr) \
    asm volatile("ldmatrix.sync.aligned.m8n8.x4.trans.shared.b16 {%0,%1,%2,%3}, [%4];" \
        : "=r"((r)[0]), "=r"((r)[1]), "=r"((r)[2]), "=r"((r)[3]) : "r"(addr))

#define MMA16816(d, a, b0v, b1v) \
    asm volatile("mma.sync.aligned.m16n8k16.row.col.f32.bf16.bf16.f32 " \
        "{%0,%1,%2,%3}, {%4,%5,%6,%7}, {%8,%9}, {%0,%1,%2,%3};" \
        : "+f"((d)[0]), "+f"((d)[1]), "+f"((d)[2]), "+f"((d)[3]) \
        : "r"((a)[0]), "r"((a)[1]), "r"((a)[2]), "r"((a)[3]), "r"(b0v), "r"(b1v))

__device__ __forceinline__ uint32_t pack_bf(float hi, float lo) {
    uint32_t d;
    asm("cvt.rn.bf16x2.f32 %0, %1, %2;" : "=r"(d) : "f"(hi), "f"(lo));
    return d;
}
__device__ __forceinline__ float bf_round(float v) {
    return __bfloat162float(__float2bfloat16(v));
}

// ---------------------------------------------------------------------------
// Kernel 1: fused PE + split:  (x + a*sin_pe + (1-a)*rel) -> (g_ah, g_al)
// ---------------------------------------------------------------------------
__global__ void pe_split_kernel(const float* __restrict__ x,
                                const float* __restrict__ rel,
                                const float* __restrict__ alphap) {
    int idx = blockIdx.x*blockDim.x + threadIdx.x;
    if (idx >= MT*(DM/2)) return;
    int m  = idx >> 9;
    int pp = idx & 511;
    int s  = m & (SS-1);
    float a = alphap[0];
    float freq = __expf(-(float)(2*pp) * (9.210340371976184f/(float)DM));
    float ang = (float)s * freq;
    float sn, cs;
    sincosf(ang, &sn, &cs);
    const float* rr = rel + (size_t)(MSL - SS + s)*DM + 2*pp;
    float2 xv = *(const float2*)(x + (size_t)idx*2);
    float om = 1.0f - a;
    float ox = xv.x + a*sn + om*rr[0];
    float oy = xv.y + a*cs + om*rr[1];
    __nv_bfloat16 hx = __float2bfloat16(ox);
    __nv_bfloat16 hy = __float2bfloat16(oy);
    __nv_bfloat16 lx = __float2bfloat16(ox - __bfloat162float(hx));
    __nv_bfloat16 ly = __float2bfloat16(oy - __bfloat162float(hy));
    *(__nv_bfloat162*)(g_ah + (size_t)idx*2) = __nv_bfloat162(hx, hy);
    *(__nv_bfloat162*)(g_al + (size_t)idx*2) = __nv_bfloat162(lx, ly);
}

// ---------------------------------------------------------------------------
// Kernel 2: fp32 -> (hi, lo) bf16 split (for weights).
// ---------------------------------------------------------------------------
__global__ void split_kernel(const float* __restrict__ src,
                             __nv_bfloat16* __restrict__ hi,
                             __nv_bfloat16* __restrict__ lo, int n4) {
    int i = blockIdx.x*blockDim.x + threadIdx.x;
    if (i >= n4) return;
    float4 v = ((const float4*)src)[i];
    __nv_bfloat16 h0 = __float2bfloat16(v.x);
    __nv_bfloat16 h1 = __float2bfloat16(v.y);
    __nv_bfloat16 h2 = __float2bfloat16(v.z);
    __nv_bfloat16 h3 = __float2bfloat16(v.w);
    __nv_bfloat16 l0 = __float2bfloat16(v.x - __bfloat162float(h0));
    __nv_bfloat16 l1 = __float2bfloat16(v.y - __bfloat162float(h1));
    __nv_bfloat16 l2 = __float2bfloat16(v.z - __bfloat162float(h2));
    __nv_bfloat16 l3 = __float2bfloat16(v.w - __bfloat162float(h3));
    __nv_bfloat162* hp = (__nv_bfloat162*)(hi + (size_t)i*4);
    __nv_bfloat162* lp = (__nv_bfloat162*)(lo + (size_t)i*4);
    hp[0] = __nv_bfloat162(h0, h1); hp[1] = __nv_bfloat162(h2, h3);
    lp[0] = __nv_bfloat162(l0, l1); lp[1] = __nv_bfloat162(l2, l3);
}

// ---------------------------------------------------------------------------
// TMA split-bf16 GEMM. Block 128x128, 256 threads, warp tile 64x32.
// K-chunk 64, double-buffered TMA (SW128), mbarrier completion.
// mode 0: merged QKV (gridDim.x=24), n0>>10 selects target; mode 3: out proj.
// ---------------------------------------------------------------------------
#define GB 16384                  // one operand tile: 128 rows x 128B (SW128)
#define GSTG (4*GB)               // AH AL BH BL = 65536
#define GEMM_SMEM (2*GSTG + 1088) // + mbars + align pad

__global__ void __launch_bounds__(256, 1) gemm_tma(
    const __grid_constant__ CUtensorMap mAh,
    const __grid_constant__ CUtensorMap mAl,
    const __grid_constant__ CUtensorMap mWh,
    const __grid_constant__ CUtensorMap mWl,
    const float* __restrict__ b0, const float* __restrict__ b1,
    const float* __restrict__ b2, float* __restrict__ outp, int mode)
{
    extern __shared__ char smem[];
    const uint32_t sb = (smem_u32(smem) + 1023) & ~1023u;
    const uint32_t mb = sb + 2*GSTG;
    const int t  = threadIdx.x;
    const int m0 = blockIdx.y * 128;
    const int n0 = blockIdx.x * 128;

    if (t == 0) { MBAR_INIT(mb, 1); MBAR_INIT(mb + 8, 1); }
    __syncthreads();

    auto issue = [&](int ck) {
        const uint32_t d   = sb + (uint32_t)(ck & 1) * GSTG;
        const uint32_t bar = mb + (uint32_t)(ck & 1) * 8;
        EXPECT_TX(bar, (uint32_t)GSTG);
        TMA2D(d + 0*GB, &mAh, ck*64, m0, bar);
        TMA2D(d + 1*GB, &mAl, ck*64, m0, bar);
        TMA2D(d + 2*GB, &mWh, ck*64, n0, bar);
        TMA2D(d + 3*GB, &mWl, ck*64, n0, bar);
    };
    if (t == 0) { issue(0); issue(1); }

    const int wid = t >> 5, l = t & 31;
    const int warpM = wid & 1;
    const int warpN = wid >> 1;
    const int q  = l >> 3, lr = l & 7;

    float acc[16][4];
    #pragma unroll
    for (int i = 0; i < 16; i++)
        #pragma unroll
        for (int j = 0; j < 4; j++) acc[i][j] = 0.f;

    // fragment row offsets (row*128); all rows == lr (mod 8) -> lane-const XOR
    uint32_t arow[4], brow[2];
    #pragma unroll
    for (int mt = 0; mt < 4; mt++) arow[mt] = (uint32_t)(warpM*64 + mt*16 + (q & 1)*8 + lr) * 128;
    #pragma unroll
    for (int np = 0; np < 2; np++) brow[np] = (uint32_t)(warpN*32 + np*16 + (q >> 1)*8 + lr) * 128;
    uint32_t axc[4], bxc[4];
    #pragma unroll
    for (int s = 0; s < 4; s++) {
        axc[s] = (uint32_t)((((q >> 1) + 2*s) ^ lr) * 16);
        bxc[s] = (uint32_t)((((q & 1) + 2*s) ^ lr) * 16);
    }

    int ph0 = 0, ph1 = 0;
    for (int ch = 0; ch < DM/64; ch++) {
        const int bsel = ch & 1;
        if (bsel == 0) { mbar_wait(mb,     (uint32_t)ph0); ph0 ^= 1; }
        else           { mbar_wait(mb + 8, (uint32_t)ph1); ph1 ^= 1; }
        const uint32_t bs = sb + (uint32_t)bsel * GSTG;

        #pragma unroll
        for (int s = 0; s < 4; s++) {
            uint32_t ah[4][4], alr[4][4];
            #pragma unroll
            for (int mt = 0; mt < 4; mt++) {
                uint32_t ao = arow[mt] + axc[s];
                LDSM4(ah[mt],  bs + 0*GB + ao);
                LDSM4(alr[mt], bs + 1*GB + ao);
            }
            uint32_t bh[2][4], bl[2][4];
            #pragma unroll
            for (int np = 0; np < 2; np++) {
                uint32_t bo = brow[np] + bxc[s];
                LDSM4(bh[np], bs + 2*GB + bo);
                LDSM4(bl[np], bs + 3*GB + bo);
            }
            #pragma unroll
            for (int mt = 0; mt < 4; mt++)
                #pragma unroll
                for (int nt = 0; nt < 4; nt++) {
                    const int np = nt >> 1, h = (nt & 1) * 2;
                    MMA16816(acc[mt*4+nt], ah[mt], bh[np][h], bh[np][h+1]);
                }
            #pragma unroll
            for (int mt = 0; mt < 4; mt++)
                #pragma unroll
                for (int nt = 0; nt < 4; nt++) {
                    const int np = nt >> 1, h = (nt & 1) * 2;
                    MMA16816(acc[mt*4+nt], ah[mt], bl[np][h], bl[np][h+1]);
                }
            #pragma unroll
            for (int mt = 0; mt < 4; mt++)
                #pragma unroll
                for (int nt = 0; nt < 4; nt++) {
                    const int np = nt >> 1, h = (nt & 1) * 2;
                    MMA16816(acc[mt*4+nt], alr[mt], bh[np][h], bh[np][h+1]);
                }
        }
        __syncthreads();
        if (t == 0 && ch + 2 < DM/64) issue(ch + 2);
    }

    // epilogue
    if (mode == 0) {
        const int which = n0 >> 10;
        const float ascale = (which == 0) ? 0.03125f : 1.0f;
        __nv_bfloat16* oh = (which == 0) ? g_qh : (which == 1) ? g_kh : g_vh;
        __nv_bfloat16* ol = (which == 0) ? g_ql : (which == 1) ? g_kl : g_vl;
        const float* bias = (which == 0) ? b0 : (which == 1) ? b1 : b2;
        const int nloc0 = n0 & 1023;
        #pragma unroll
        for (int nt = 0; nt < 4; nt++) {
            const int n = nloc0 + warpN*32 + nt*8 + (l & 3)*2;
            const float bx = bias[n], by = bias[n+1];
            #pragma unroll
            for (int mt = 0; mt < 4; mt++) {
                const float* d = acc[mt*4 + nt];
                #pragma unroll
                for (int half = 0; half < 2; half++) {
                    const int m = m0 + warpM*64 + mt*16 + (l >> 2) + half*8;
                    float vx = (d[half*2 + 0] + bx) * ascale;
                    float vy = (d[half*2 + 1] + by) * ascale;
                    const int bb = m >> 11, s = m & (SS-1);
                    const int hh = n >> 6, dd = n & 63;
                    size_t o = (size_t)((bb*NH + hh)*SS + s)*HD + dd;
                    __nv_bfloat16 hx = __float2bfloat16(vx);
                    __nv_bfloat16 hy = __float2bfloat16(vy);
                    __nv_bfloat16 lx = __float2bfloat16(vx - __bfloat162float(hx));
                    __nv_bfloat16 ly = __float2bfloat16(vy - __bfloat162float(hy));
                    *(__nv_bfloat162*)(oh + o) = __nv_bfloat162(hx, hy);
                    *(__nv_bfloat162*)(ol + o) = __nv_bfloat162(lx, ly);
                }
            }
        }
    } else {
        #pragma unroll
        for (int nt = 0; nt < 4; nt++) {
            const int n = n0 + warpN*32 + nt*8 + (l & 3)*2;
            const float bx = b0[n], by = b0[n+1];
            #pragma unroll
            for (int mt = 0; mt < 4; mt++) {
                const float* d = acc[mt*4 + nt];
                #pragma unroll
                for (int half = 0; half < 2; half++) {
                    const int m = m0 + warpM*64 + mt*16 + (l >> 2) + half*8;
                    float2 v;
                    v.x = d[half*2 + 0] + bx;
                    v.y = d[half*2 + 1] + by;
                    *(float2*)&outp[(size_t)m*DM + n] = v;
                }
            }
        }
    }
}

// ---------------------------------------------------------------------------
// Flash attention on tensor cores (split-bf16, online softmax), TMA staging.
// Block: 128 queries x one (b,h); 256 threads = 8 warps, warp = 16 q rows.
// KV tile 64, double-buffered TMA (SW128). Same math as round 5.
// ---------------------------------------------------------------------------
#define FQB 16384                 // Q array tile: 128 rows x 128B
#define FKB 8192                  // KV array tile: 64 rows x 128B
#define FSTG (4*FKB)              // KH KL VH VL = 32768
#define FL_SMEM (2*FQB + 2*FSTG + 1088)

__global__ void __launch_bounds__(256, 1) flash_tma(
    const __grid_constant__ CUtensorMap mQh,
    const __grid_constant__ CUtensorMap mQl,
    const __grid_constant__ CUtensorMap mKh,
    const __grid_constant__ CUtensorMap mKl,
    const __grid_constant__ CUtensorMap mVh,
    const __grid_constant__ CUtensorMap mVl)
{
    extern __shared__ char fsm[];
    const uint32_t sb  = (smem_u32(fsm) + 1023) & ~1023u;
    const uint32_t kvb = sb + 2*FQB;
    const uint32_t mbq = sb + 2*FQB + 2*FSTG;
    const int bh = blockIdx.y;
    const int q0 = blockIdx.x * 128;
    const int row0 = bh * SS;               // tensor row base for this (b,h)
    const int t = threadIdx.x, wid = t >> 5, l = t & 31;
    const int q = l >> 3, lr = l & 7;
    const int wq0 = wid * 16;

    if (t == 0) { MBAR_INIT(mbq, 1); MBAR_INIT(mbq + 8, 1); MBAR_INIT(mbq + 16, 1); }
    __syncthreads();

    auto kvissue = [&](int ti) {
        const uint32_t d   = kvb + (uint32_t)(ti & 1) * FSTG;
        const uint32_t bar = mbq + 8 + (uint32_t)(ti & 1) * 8;
        EXPECT_TX(bar, (uint32_t)FSTG);
        const int y = row0 + ti*64;
        TMA2D(d + 0*FKB, &mKh, 0, y, bar);
        TMA2D(d + 1*FKB, &mKl, 0, y, bar);
        TMA2D(d + 2*FKB, &mVh, 0, y, bar);
        TMA2D(d + 3*FKB, &mVl, 0, y, bar);
    };
    if (t == 0) {
        EXPECT_TX(mbq, (uint32_t)(2*FQB));
        TMA2D(sb,       &mQh, 0, row0 + q0, mbq);
        TMA2D(sb + FQB, &mQl, 0, row0 + q0, mbq);
        kvissue(0);
        kvissue(1);
    }

    mbar_wait(mbq, 0);

    // Q fragments (persistent): row = wq0 + (q&1)*8 + lr, col16 = (q>>1)+2kt
    uint32_t qhf[4][4], qlf[4][4];
    {
        const uint32_t qrow = (uint32_t)(wq0 + (q & 1)*8 + lr) * 128;
        #pragma unroll
        for (int kt = 0; kt < 4; kt++) {
            const uint32_t c = (uint32_t)((((q >> 1) + 2*kt) ^ lr) * 16);
            LDSM4(qhf[kt], sb + qrow + c);
            LDSM4(qlf[kt], sb + FQB + qrow + c);
        }
    }

    // fragment address invariants for K and V
    uint32_t krow[4], vrow[4], kxc[4], vxc[4];
    #pragma unroll
    for (int np = 0; np < 4; np++) krow[np] = (uint32_t)(np*16 + (q >> 1)*8 + lr) * 128;
    #pragma unroll
    for (int kt = 0; kt < 4; kt++) vrow[kt] = (uint32_t)(kt*16 + (q & 1)*8 + lr) * 128;
    #pragma unroll
    for (int kt = 0; kt < 4; kt++) kxc[kt] = (uint32_t)((((q & 1) + 2*kt) ^ lr) * 16);
    #pragma unroll
    for (int g = 0; g < 4; g++)  vxc[g]  = (uint32_t)(((2*g + (q >> 1)) ^ lr) * 16);

    float oacc[8][4];
    #pragma unroll
    for (int i = 0; i < 8; i++)
        #pragma unroll
        for (int j = 0; j < 4; j++) oacc[i][j] = 0.f;
    float mprev0 = -1e30f, mprev1 = -1e30f, lsum0 = 0.f, lsum1 = 0.f;

    int kvph0 = 0, kvph1 = 0;
    for (int ti = 0; ti < SS/64; ti++) {
        const int bsel = ti & 1;
        if (bsel == 0) { mbar_wait(mbq + 8,  (uint32_t)kvph0); kvph0 ^= 1; }
        else           { mbar_wait(mbq + 16, (uint32_t)kvph1); kvph1 ^= 1; }
        const uint32_t kb = kvb + (uint32_t)bsel * FSTG;

        float sacc[8][4];
        #pragma unroll
        for (int i = 0; i < 8; i++)
            #pragma unroll
            for (int j = 0; j < 4; j++) sacc[i][j] = 0.f;

        #pragma unroll
        for (int kt = 0; kt < 4; kt++) {
            uint32_t khf[4][4], klf[4][4];
            #pragma unroll
            for (int np = 0; np < 4; np++) {
                uint32_t ba = krow[np] + kxc[kt];
                LDSM4(khf[np], kb + 0*FKB + ba);
                LDSM4(klf[np], kb + 1*FKB + ba);
            }
            #pragma unroll
            for (int nt = 0; nt < 8; nt++) {
                const int np = nt >> 1, h = (nt & 1)*2;
                MMA16816(sacc[nt], qhf[kt], khf[np][h], khf[np][h+1]);
            }
            #pragma unroll
            for (int nt = 0; nt < 8; nt++) {
                const int np = nt >> 1, h = (nt & 1)*2;
                MMA16816(sacc[nt], qhf[kt], klf[np][h], klf[np][h+1]);
            }
            #pragma unroll
            for (int nt = 0; nt < 8; nt++) {
                const int np = nt >> 1, h = (nt & 1)*2;
                MMA16816(sacc[nt], qlf[kt], khf[np][h], khf[np][h+1]);
            }
        }

        float m0 = sacc[0][0], m1 = sacc[0][2];
        #pragma unroll
        for (int nt = 0; nt < 8; nt++) {
            m0 = fmaxf(m0, fmaxf(sacc[nt][0], sacc[nt][1]));
            m1 = fmaxf(m1, fmaxf(sacc[nt][2], sacc[nt][3]));
        }
        m0 = fmaxf(m0, __shfl_xor_sync(0xffffffffu, m0, 1));
        m0 = fmaxf(m0, __shfl_xor_sync(0xffffffffu, m0, 2));
        m1 = fmaxf(m1, __shfl_xor_sync(0xffffffffu, m1, 1));
        m1 = fmaxf(m1, __shfl_xor_sync(0xffffffffu, m1, 2));

        const float mn0 = fmaxf(mprev0, m0);
        const float mn1 = fmaxf(mprev1, m1);
        const float a0 = __expf(mprev0 - mn0);
        const float a1 = __expf(mprev1 - mn1);
        mprev0 = mn0; mprev1 = mn1;

        float rs0 = 0.f, rs1 = 0.f;
        #pragma unroll
        for (int nt = 0; nt < 8; nt++) {
            sacc[nt][0] = __expf(sacc[nt][0] - mn0);
            sacc[nt][1] = __expf(sacc[nt][1] - mn0);
            sacc[nt][2] = __expf(sacc[nt][2] - mn1);
            sacc[nt][3] = __expf(sacc[nt][3] - mn1);
            rs0 += sacc[nt][0] + sacc[nt][1];
            rs1 += sacc[nt][2] + sacc[nt][3];
        }
        rs0 += __shfl_xor_sync(0xffffffffu, rs0, 1);
        rs0 += __shfl_xor_sync(0xffffffffu, rs0, 2);
        rs1 += __shfl_xor_sync(0xffffffffu, rs1, 1);
        rs1 += __shfl_xor_sync(0xffffffffu, rs1, 2);
        lsum0 = lsum0*a0 + rs0;
        lsum1 = lsum1*a1 + rs1;
        #pragma unroll
        for (int nj = 0; nj < 8; nj++) {
            oacc[nj][0] *= a0; oacc[nj][1] *= a0;
            oacc[nj][2] *= a1; oacc[nj][3] *= a1;
        }

        #pragma unroll
        for (int kt = 0; kt < 4; kt++) {
            uint32_t ph[4], pl[4];
            #pragma unroll
            for (int e = 0; e < 4; e++) {
                const float* s0 = sacc[2*kt + (e >> 1)];
                const float x0 = s0[(e & 1)*2], x1 = s0[(e & 1)*2 + 1];
                ph[e] = pack_bf(x1, x0);
                pl[e] = pack_bf(x1 - bf_round(x1), x0 - bf_round(x0));
            }
            uint32_t vhf[4][4], vlf[4][4];
            #pragma unroll
            for (int g = 0; g < 4; g++) {
                uint32_t va = vrow[kt] + vxc[g];
                LDSM4T(vhf[g], kb + 2*FKB + va);
                LDSM4T(vlf[g], kb + 3*FKB + va);
            }
            #pragma unroll
            for (int nj = 0; nj < 8; nj++) {
                const int g = nj >> 1, o = (nj & 1)*2;
                MMA16816(oacc[nj], ph, vhf[g][o], vhf[g][o+1]);
            }
            #pragma unroll
            for (int nj = 0; nj < 8; nj++) {
                const int g = nj >> 1, o = (nj & 1)*2;
                MMA16816(oacc[nj], ph, vlf[g][o], vlf[g][o+1]);
            }
            #pragma unroll
            for (int nj = 0; nj < 8; nj++) {
                const int g = nj >> 1, o = (nj & 1)*2;
                MMA16816(oacc[nj], pl, vhf[g][o], vhf[g][o+1]);
            }
        }

        __syncthreads();
        if (t == 0 && ti + 2 < SS/64) kvissue(ti + 2);
    }

    const float inv0 = 1.0f / lsum0;
    const float inv1 = 1.0f / lsum1;
    const int r0 = q0 + wq0 + (l >> 2);
    const int bb = bh >> 4, hh = bh & 15;
    #pragma unroll
    for (int nj = 0; nj < 8; nj++) {
        const int col = hh*HD + nj*8 + (l & 3)*2;
        {
            const float e0 = oacc[nj][0]*inv0, e1 = oacc[nj][1]*inv0;
            __nv_bfloat16 h0 = __float2bfloat16(e0), h1 = __float2bfloat16(e1);
            __nv_bfloat16 l0 = __float2bfloat16(e0 - __bfloat162float(h0));
            __nv_bfloat16 l1 = __float2bfloat16(e1 - __bfloat162float(h1));
            size_t o = (size_t)(bb*SS + r0)*DM + col;
            *(__nv_bfloat162*)(g_ah + o) = __nv_bfloat162(h0, h1);
            *(__nv_bfloat162*)(g_al + o) = __nv_bfloat162(l0, l1);
        }
        {
            const float e0 = oacc[nj][2]*inv1, e1 = oacc[nj][3]*inv1;
            __nv_bfloat16 h0 = __float2bfloat16(e0), h1 = __float2bfloat16(e1);
            __nv_bfloat16 l0 = __float2bfloat16(e0 - __bfloat162float(h0));
            __nv_bfloat16 l1 = __float2bfloat16(e1 - __bfloat162float(h1));
            size_t o = (size_t)(bb*SS + r0 + 8)*DM + col;
            *(__nv_bfloat162*)(g_ah + o) = __nv_bfloat162(h0, h1);
            *(__nv_bfloat162*)(g_al + o) = __nv_bfloat162(l0, l1);
        }
    }
}

// ---------------------------------------------------------------------------
// host: tensor-map construction via driver entry point (no -lcuda needed)
// ---------------------------------------------------------------------------
typedef CUresult (CUDAAPI *PFN_encodeTiled)(
    CUtensorMap*, CUtensorMapDataType, cuuint32_t, void*,
    const cuuint64_t*, const cuuint64_t*, const cuuint32_t*, const cuuint32_t*,
    CUtensorMapInterleave, CUtensorMapSwizzle, CUtensorMapL2promotion,
    CUtensorMapFloatOOBfill);

static PFN_encodeTiled get_encoder() {
    static PFN_encodeTiled fn = nullptr;
    if (!fn) {
        void* p = nullptr;
        cudaDriverEntryPointQueryResult qr;
        cudaGetDriverEntryPoint("cuTensorMapEncodeTiled", &p, cudaEnableDefault, &qr);
        fn = (PFN_encodeTiled)p;
    }
    return fn;
}

static void mk2d(CUtensorMap* m, void* base, uint64_t d0, uint64_t rows,
                 uint32_t b0, uint32_t b1) {
    cuuint64_t dims[2]    = {d0, rows};
    cuuint64_t strides[1] = {d0 * 2};     // bytes
    cuuint32_t box[2]     = {b0, b1};
    cuuint32_t es[2]      = {1, 1};
    get_encoder()(m, CU_TENSOR_MAP_DATA_TYPE_BFLOAT16, 2, base,
                  dims, strides, box, es,
                  CU_TENSOR_MAP_INTERLEAVE_NONE, CU_TENSOR_MAP_SWIZZLE_128B,
                  CU_TENSOR_MAP_L2_PROMOTION_L2_128B,
                  CU_TENSOR_MAP_FLOAT_OOB_FILL_NONE);
}

extern "C" void kernel_launch(void* const* d_in, const int* in_sizes, int n_in,
                              void* d_out, int out_size) {
    const float* x     = (const float*)d_in[0];
    const float* rel   = (const float*)d_in[1];
    const float* alpha = (const float*)d_in[2];
    const float* Wq    = (const float*)d_in[3];
    const float* bq    = (const float*)d_in[4];
    const float* Wk    = (const float*)d_in[5];
    const float* bk    = (const float*)d_in[6];
    const float* Wv    = (const float*)d_in[7];
    const float* bv    = (const float*)d_in[8];
    const float* Wo    = (const float*)d_in[9];
    const float* bo    = (const float*)d_in[10];
    float* out = (float*)d_out;

    cudaFuncSetAttribute(gemm_tma,  cudaFuncAttributeMaxDynamicSharedMemorySize, GEMM_SMEM);
    cudaFuncSetAttribute(flash_tma, cudaFuncAttributeMaxDynamicSharedMemorySize, FL_SMEM);

    void *ah, *al, *wh, *wl, *qh, *ql, *kh, *kl, *vh, *vl;
    cudaGetSymbolAddress(&ah, g_ah);
    cudaGetSymbolAddress(&al, g_al);
    cudaGetSymbolAddress(&wh, g_wh);
    cudaGetSymbolAddress(&wl, g_wl);
    cudaGetSymbolAddress(&qh, g_qh);
    cudaGetSymbolAddress(&ql, g_ql);
    cudaGetSymbolAddress(&kh, g_kh);
    cudaGetSymbolAddress(&kl, g_kl);
    cudaGetSymbolAddress(&vh, g_vh);
    cudaGetSymbolAddress(&vl, g_vl);

    CUtensorMap mAh, mAl, mWh, mWl, mQh, mQl, mKh, mKl, mVh, mVl;
    mk2d(&mAh, ah, DM, MT,          64, 128);
    mk2d(&mAl, al, DM, MT,          64, 128);
    mk2d(&mWh, wh, DM, 3*DM,        64, 128);
    mk2d(&mWl, wl, DM, 3*DM,        64, 128);
    mk2d(&mQh, qh, HD, BB*NH*SS,    64, 128);
    mk2d(&mQl, ql, HD, BB*NH*SS,    64, 128);
    mk2d(&mKh, kh, HD, BB*NH*SS,    64, 64);
    mk2d(&mKl, kl, HD, BB*NH*SS,    64, 64);
    mk2d(&mVh, vh, HD, BB*NH*SS,    64, 64);
    mk2d(&mVl, vl, HD, BB*NH*SS,    64, 64);

    pe_split_kernel<<<(MT*(DM/2) + 255)/256, 256>>>(x, rel, alpha);

    const int nW4 = DM*DM/4;
    split_kernel<<<(nW4 + 255)/256, 256>>>(Wq, (__nv_bfloat16*)wh,            (__nv_bfloat16*)wl,            nW4);
    split_kernel<<<(nW4 + 255)/256, 256>>>(Wk, (__nv_bfloat16*)wh + DM*DM,    (__nv_bfloat16*)wl + DM*DM,    nW4);
    split_kernel<<<(nW4 + 255)/256, 256>>>(Wv, (__nv_bfloat16*)wh + 2*DM*DM,  (__nv_bfloat16*)wl + 2*DM*DM,  nW4);

    gemm_tma<<<dim3(3*DM/128, MT/128), 256, GEMM_SMEM>>>(
        mAh, mAl, mWh, mWl, bq, bk, bv, nullptr, 0);

    flash_tma<<<dim3(SS/128, BB*NH), 256, FL_SMEM>>>(mQh, mQl, mKh, mKl, mVh, mVl);

    split_kernel<<<(nW4 + 255)/256, 256>>>(Wo, (__nv_bfloat16*)wh, (__nv_bfloat16*)wl, nW4);
    gemm_tma<<<dim3(DM/128, MT/128), 256, GEMM_SMEM>>>(
        mAh, mAl, mWh, mWl, bo, bo, bo, out, 3);
}